// round 12
// baseline (speedup 1.0000x reference)
#include <cuda_runtime.h>
#include <math.h>

#define C_DIM 128
#define S_DIM 4096
#define HW 176          // 16 * 11
#define HW4 44          // HW / 4
#define B_SEG 32
#define O_DIM 256
#define OSLICE 32       // o per conv-slice block
#define NSLICE 8        // conv slices per b (last NSLICE arrivers)
#define CCHUNK 64       // W staging chunk (8 KB)
#define PART_LEN 44
#define GEM_EPS 1e-6f
#define NEG_INF -3.402823466e38f

// scratch
__device__ float g_pooled[B_SEG * C_DIM * HW];               // [b][c][hw]
__device__ float g_ypow[B_SEG * NSLICE * OSLICE * HW];       // [b*8+sl][o][hw]
__device__ int   g_cnt[B_SEG];

__device__ __forceinline__ float4 max4(float4 a, float4 b) {
    float4 r;
    r.x = fmaxf(a.x, b.x); r.y = fmaxf(a.y, b.y);
    r.z = fmaxf(a.z, b.z); r.w = fmaxf(a.w, b.w);
    return r;
}
__device__ __forceinline__ unsigned long long pack2(float v) {
    unsigned long long r;
    asm("mov.b64 %0, {%1, %1};" : "=l"(r) : "f"(v));
    return r;
}
__device__ __forceinline__ void unpack2(unsigned long long v, float& lo, float& hi) {
    asm("mov.b64 {%0, %1}, %2;" : "=f"(lo), "=f"(hi) : "l"(v));
}
__device__ __forceinline__ void ffma2(unsigned long long& d,
                                      unsigned long long a, unsigned long long b) {
    asm("fma.rn.f32x2 %0, %1, %2, %0;" : "+l"(d) : "l"(a), "l"(b));
}
// GeM power, fast path for pe == 6.5: (v^3)^2 * sqrt(v).
__device__ __forceinline__ float gem_pow(float x, float pe, bool fast65) {
    float v = fmaxf(x, GEM_EPS);
    if (fast65) {
        float v3 = v * v * v;
        return v3 * v3 * sqrtf(v);
    }
    return exp2f(pe * __log2f(v));
}

__global__ void zero_cnt_kernel() {
    if (threadIdx.x < B_SEG) g_cnt[threadIdx.x] = 0;
}

// ---------------------------------------------------------------------------
// Fused kernel, SMALL SMEM (~8.5 KB): union of the segmax staging buffer and
// the conv W chunk; ypow goes through global scratch. Grid 4096, b-major.
// Last NSLICE arrivers per b compute a 32-o conv+GeM slice for b.
// ---------------------------------------------------------------------------
__global__ void __launch_bounds__(352) fused_kernel(
    const float* __restrict__ x, const int* __restrict__ seqL,
    const float* __restrict__ Wmat, const float* __restrict__ p,
    float* __restrict__ out)
{
    __shared__ int sh[3];                                 // s0, len, order
    __shared__ __align__(16) float sbuf[CCHUNK * OSLICE]; // 8 KB union:
                                                          //   phase1: smax (5.6 KB)
                                                          //   phase2: ws chunk
    float4* smax = reinterpret_cast<float4*>(sbuf);

    int blk = blockIdx.x;
    int b = blk >> 7;            // b-major
    int c = blk & (C_DIM - 1);
    int tid = threadIdx.x;

    // ---- Phase 1: segment max ----
    if (tid == 0) {
        int s0 = 0;
        #pragma unroll
        for (int i = 0; i < B_SEG; i++) s0 += (i < b) ? seqL[i] : 0;
        sh[0] = s0;
        sh[1] = seqL[b];
    }
    __syncthreads();

    {
        int sg  = tid / HW4;
        int col = tid % HW4;
        int s0  = sh[0];
        int len = sh[1];

        const float4* bp = reinterpret_cast<const float4*>(x)
                         + (size_t)c * (S_DIM * HW4) + (size_t)s0 * HW4 + col;

        float4 m = make_float4(NEG_INF, NEG_INF, NEG_INF, NEG_INF);
        int s = sg;
        for (; s + 56 < len; s += 64) {
            float4 a0 = __ldcs(&bp[(size_t)(s +  0) * HW4]);
            float4 a1 = __ldcs(&bp[(size_t)(s +  8) * HW4]);
            float4 a2 = __ldcs(&bp[(size_t)(s + 16) * HW4]);
            float4 a3 = __ldcs(&bp[(size_t)(s + 24) * HW4]);
            float4 a4 = __ldcs(&bp[(size_t)(s + 32) * HW4]);
            float4 a5 = __ldcs(&bp[(size_t)(s + 40) * HW4]);
            float4 a6 = __ldcs(&bp[(size_t)(s + 48) * HW4]);
            float4 a7 = __ldcs(&bp[(size_t)(s + 56) * HW4]);
            m = max4(m, max4(max4(max4(a0, a1), max4(a2, a3)),
                             max4(max4(a4, a5), max4(a6, a7))));
        }
        for (; s < len; s += 8) {
            m = max4(m, __ldcs(&bp[(size_t)s * HW4]));
        }
        smax[sg * HW4 + col] = m;
    }
    __syncthreads();

    if (tid < HW4) {
        float4 r = smax[tid];
        #pragma unroll
        for (int g = 1; g < 8; g++) r = max4(r, smax[g * HW4 + tid]);
        reinterpret_cast<float4*>(g_pooled)[(size_t)(b * C_DIM + c) * HW4 + tid] = r;
    }
    __syncthreads();

    // ---- Publish ----
    if (tid == 0) {
        __threadfence();
        sh[2] = atomicAdd(&g_cnt[b], 1);
    }
    __syncthreads();
    int order = sh[2];
    if (order < C_DIM - NSLICE) return;

    int sl = order - (C_DIM - NSLICE);   // 0..7
    int o0 = sl * OSLICE;

    // Wait for all 128 producers of this b
    if (tid == 0) {
        while (*(volatile int*)&g_cnt[b] != C_DIM) __nanosleep(64);
        __threadfence();
    }
    __syncthreads();

    // ---- Phase 2: conv slice [32 o] x [176 hw] for batch b ----
    int half = tid / HW;        // 0/1 -> o sub-slice of 16
    int hw   = tid % HW;
    float* yreg = g_ypow + (size_t)(b * NSLICE + sl) * (OSLICE * HW);

    unsigned long long acc[8];
    #pragma unroll
    for (int k = 0; k < 8; k++) acc[k] = 0ULL;

    const float* pb = g_pooled + (size_t)b * C_DIM * HW + hw;

    for (int c0 = 0; c0 < C_DIM; c0 += CCHUNK) {
        // stage W chunk [64 cc][32 o] (transposed) into sbuf
        for (int i = tid; i < CCHUNK * OSLICE; i += 352) {
            int cc = i >> 5;
            int j  = i & (OSLICE - 1);
            sbuf[i] = Wmat[(o0 + j) * C_DIM + c0 + cc];
        }
        __syncthreads();

        const float* wsh = sbuf + half * 16;
        #pragma unroll 4
        for (int cc = 0; cc < CCHUNK; cc++) {
            unsigned long long pv2 = pack2(__ldg(&pb[(size_t)(c0 + cc) * HW]));
            const ulonglong2* wr = reinterpret_cast<const ulonglong2*>(
                wsh + cc * OSLICE);
            ulonglong2 w0 = wr[0];
            ulonglong2 w1 = wr[1];
            ulonglong2 w2 = wr[2];
            ulonglong2 w3 = wr[3];
            ffma2(acc[0], pv2, w0.x); ffma2(acc[1], pv2, w0.y);
            ffma2(acc[2], pv2, w1.x); ffma2(acc[3], pv2, w1.y);
            ffma2(acc[4], pv2, w2.x); ffma2(acc[5], pv2, w2.y);
            ffma2(acc[6], pv2, w3.x); ffma2(acc[7], pv2, w3.y);
        }
        __syncthreads();
    }

    {
        float pe = __ldg(&p[hw / PART_LEN]);
        bool fast65 = (pe == 6.5f);
        int ob = half * 16;
        #pragma unroll
        for (int k = 0; k < 8; k++) {
            float lo, hi;
            unpack2(acc[k], lo, hi);
            yreg[(ob + 2 * k + 0) * HW + hw] = gem_pow(lo, pe, fast65);
            yreg[(ob + 2 * k + 1) * HW + hw] = gem_pow(hi, pe, fast65);
        }
    }
    __syncthreads();   // global writes by own block visible after sync

    // 128 threads: one per (o_local, part)
    if (tid < OSLICE * 4) {
        int ol   = tid >> 2;
        int part = tid & 3;
        const float* yp = yreg + ol * HW + part * PART_LEN;
        float sum = 0.0f;
        #pragma unroll
        for (int k = 0; k < PART_LEN; k++) sum += yp[k];
        float pe = __ldg(&p[part]);
        float mean = sum * (1.0f / (float)PART_LEN);
        float g = (mean > 0.0f) ? exp2f(__log2f(mean) / pe) : 0.0f;
        out[((size_t)b * O_DIM + o0 + ol) * 4 + part] = g;
    }
}

extern "C" void kernel_launch(void* const* d_in, const int* in_sizes, int n_in,
                              void* d_out, int out_size)
{
    const float* x    = (const float*)d_in[0];
    const int*   seqL = (const int*)d_in[1];
    const float* Wm   = (const float*)d_in[2];
    const float* p    = (const float*)d_in[3];
    float* out = (float*)d_out;

    zero_cnt_kernel<<<1, 32>>>();
    fused_kernel<<<B_SEG * C_DIM, 352>>>(x, seqL, Wm, p, out);
}

// round 13
// speedup vs baseline: 1.2530x; 1.2530x over previous
#include <cuda_runtime.h>
#include <math.h>

#define C_DIM 128
#define S_DIM 4096
#define HW 176          // 16 * 11
#define HW4 44          // HW / 4
#define B_SEG 32
#define O_DIM 256
#define OW 32           // o per conv block
#define CPIPE 8
#define PART_LEN 44
#define GEM_EPS 1e-6f
#define NEG_INF -3.402823466e38f

// scratch: pooled[b][c][hw]
__device__ float g_pooled[B_SEG * C_DIM * HW];

__device__ __forceinline__ float4 max4(float4 a, float4 b) {
    float4 r;
    r.x = fmaxf(a.x, b.x); r.y = fmaxf(a.y, b.y);
    r.z = fmaxf(a.z, b.z); r.w = fmaxf(a.w, b.w);
    return r;
}
__device__ __forceinline__ unsigned long long pack2(float v) {
    unsigned long long r;
    asm("mov.b64 %0, {%1, %1};" : "=l"(r) : "f"(v));
    return r;
}
__device__ __forceinline__ void unpack2(unsigned long long v, float& lo, float& hi) {
    asm("mov.b64 {%0, %1}, %2;" : "=f"(lo), "=f"(hi) : "l"(v));
}
__device__ __forceinline__ void ffma2(unsigned long long& d,
                                      unsigned long long a, unsigned long long b) {
    asm("fma.rn.f32x2 %0, %1, %2, %0;" : "+l"(d) : "l"(a), "l"(b));
}
// GeM power, fast path for pe == 6.5: (v^3)^2 * sqrt(v).
__device__ __forceinline__ float gem_pow(float x, float pe, bool fast65) {
    float v = fmaxf(x, GEM_EPS);
    if (fast65) {
        float v3 = v * v * v;
        return v3 * v3 * sqrtf(v);
    }
    return exp2f(pe * __log2f(v));
}

// ---------------------------------------------------------------------------
// Kernel 1: ragged segment max — EXACT R7 config (58.7 us, ~6.3 TB/s).
// ---------------------------------------------------------------------------
__global__ void __launch_bounds__(352) seg_max_kernel(
    const float* __restrict__ x, const int* __restrict__ seqL)
{
    int blk = blockIdx.x;
    int b = blk & (B_SEG - 1);
    int c = blk >> 5;

    __shared__ int sh[2];
    __shared__ float4 sm[8 * HW4];

    if (threadIdx.x == 0) {
        int s0 = 0;
        #pragma unroll
        for (int i = 0; i < B_SEG; i++) s0 += (i < b) ? seqL[i] : 0;
        sh[0] = s0;
        sh[1] = seqL[b];
    }
    __syncthreads();

    int tid = threadIdx.x;
    int sg  = tid / HW4;
    int col = tid % HW4;

    int s0  = sh[0];
    int len = sh[1];

    const float4* bp = reinterpret_cast<const float4*>(x)
                     + (size_t)c * (S_DIM * HW4) + (size_t)s0 * HW4 + col;

    float4 m = make_float4(NEG_INF, NEG_INF, NEG_INF, NEG_INF);
    int s = sg;
    for (; s + 56 < len; s += 64) {
        float4 a0 = __ldcs(&bp[(size_t)(s +  0) * HW4]);
        float4 a1 = __ldcs(&bp[(size_t)(s +  8) * HW4]);
        float4 a2 = __ldcs(&bp[(size_t)(s + 16) * HW4]);
        float4 a3 = __ldcs(&bp[(size_t)(s + 24) * HW4]);
        float4 a4 = __ldcs(&bp[(size_t)(s + 32) * HW4]);
        float4 a5 = __ldcs(&bp[(size_t)(s + 40) * HW4]);
        float4 a6 = __ldcs(&bp[(size_t)(s + 48) * HW4]);
        float4 a7 = __ldcs(&bp[(size_t)(s + 56) * HW4]);
        m = max4(m, max4(max4(max4(a0, a1), max4(a2, a3)),
                         max4(max4(a4, a5), max4(a6, a7))));
    }
    for (; s < len; s += 8) {
        m = max4(m, __ldcs(&bp[(size_t)s * HW4]));
    }

    sm[sg * HW4 + col] = m;
    __syncthreads();

    if (tid < HW4) {
        float4 r = sm[tid];
        #pragma unroll
        for (int g = 1; g < 8; g++) r = max4(r, sm[g * HW4 + tid]);
        reinterpret_cast<float4*>(g_pooled)[(size_t)(b * C_DIM + c) * HW4 + tid] = r;
    }
}

// ---------------------------------------------------------------------------
// Kernel 2: conv + GeM, load-instruction-minimized.
// Grid (8 o-blocks of 32, 32 b) = 256 blocks, 176 threads = 4 o-groups x 44
// hw-quads. Thread = 4 hw x 8 o: per cc only 3 load instrs (1 LDG.128 pooled
// quad + 2 broadcast LDS.128 of W) for 32 MACs (16 FFMA2). Pooled prefetch
// depth 8. GeM via per-thread partial sums + smem reduction.
// ---------------------------------------------------------------------------
__global__ void __launch_bounds__(176) conv_gem_kernel(
    const float* __restrict__ Wmat, const float* __restrict__ p,
    float* __restrict__ out)
{
    __shared__ __align__(16) float ws[C_DIM * OW];   // [c][o], 16 KB
    __shared__ float red[176 * 8];                   // [tid][o_in_grp], 5.5 KB
    __shared__ float pp[4];

    int b   = blockIdx.y;
    int o0  = blockIdx.x * OW;
    int tid = threadIdx.x;
    int grp = tid / HW4;          // 0..3 -> 8-o group
    int q   = tid % HW4;          // hw quad 0..43

    if (tid < 4) pp[tid] = p[tid];
    for (int i = tid; i < C_DIM * OW; i += 176) {
        int cc = i >> 5;
        int j  = i & (OW - 1);
        ws[i] = Wmat[(o0 + j) * C_DIM + cc];
    }
    __syncthreads();

    unsigned long long acc[16];   // [h 0..3][opair 0..3]
    #pragma unroll
    for (int k = 0; k < 16; k++) acc[k] = 0ULL;

    const float4* pb = reinterpret_cast<const float4*>(
        g_pooled + (size_t)b * C_DIM * HW) + q;
    const float* wg = ws + grp * 8;

    float4 pv[CPIPE];
    #pragma unroll
    for (int j = 0; j < CPIPE; j++)
        pv[j] = __ldg(&pb[(size_t)j * HW4]);

    #pragma unroll
    for (int c0 = 0; c0 < C_DIM; c0 += CPIPE) {
        float4 nv[CPIPE];
        if (c0 + CPIPE < C_DIM) {
            #pragma unroll
            for (int j = 0; j < CPIPE; j++)
                nv[j] = __ldg(&pb[(size_t)(c0 + CPIPE + j) * HW4]);
        }
        #pragma unroll
        for (int j = 0; j < CPIPE; j++) {
            const ulonglong2* wr = reinterpret_cast<const ulonglong2*>(
                wg + (c0 + j) * OW);
            ulonglong2 w0 = wr[0];   // o pairs 0,1
            ulonglong2 w1 = wr[1];   // o pairs 2,3
            unsigned long long px = pack2(pv[j].x);
            unsigned long long py = pack2(pv[j].y);
            unsigned long long pz = pack2(pv[j].z);
            unsigned long long pw = pack2(pv[j].w);
            ffma2(acc[ 0], px, w0.x); ffma2(acc[ 1], px, w0.y);
            ffma2(acc[ 2], px, w1.x); ffma2(acc[ 3], px, w1.y);
            ffma2(acc[ 4], py, w0.x); ffma2(acc[ 5], py, w0.y);
            ffma2(acc[ 6], py, w1.x); ffma2(acc[ 7], py, w1.y);
            ffma2(acc[ 8], pz, w0.x); ffma2(acc[ 9], pz, w0.y);
            ffma2(acc[10], pz, w1.x); ffma2(acc[11], pz, w1.y);
            ffma2(acc[12], pw, w0.x); ffma2(acc[13], pw, w0.y);
            ffma2(acc[14], pw, w1.x); ffma2(acc[15], pw, w1.y);
        }
        #pragma unroll
        for (int j = 0; j < CPIPE; j++) pv[j] = nv[j];
    }

    // GeM elementwise power + partial sum over this thread's 4 hw.
    // hw = 4q..4q+3 all in part q/11 (44 = 4*11).
    {
        float pe = pp[q / 11];
        bool fast65 = (pe == 6.5f);
        float s[8];
        #pragma unroll
        for (int o = 0; o < 8; o++) s[o] = 0.0f;
        #pragma unroll
        for (int h = 0; h < 4; h++) {
            #pragma unroll
            for (int k = 0; k < 4; k++) {
                float lo, hi;
                unpack2(acc[h * 4 + k], lo, hi);
                s[2 * k + 0] += gem_pow(lo, pe, fast65);
                s[2 * k + 1] += gem_pow(hi, pe, fast65);
            }
        }
        #pragma unroll
        for (int o = 0; o < 8; o++) red[tid * 8 + o] = s[o];
    }
    __syncthreads();

    // 128 threads: one per (grp, o_in_grp, part); sum 11 quad-partials.
    if (tid < 128) {
        int g    = tid >> 5;         // 0..3
        int rem  = tid & 31;
        int o    = rem >> 2;         // 0..7
        int part = rem & 3;
        const float* rp = red + (g * HW4 + part * 11) * 8 + o;
        float sum = 0.0f;
        #pragma unroll
        for (int j = 0; j < 11; j++) sum += rp[j * 8];
        float pe = pp[part];
        float mean = sum * (1.0f / (float)PART_LEN);
        float gv = (mean > 0.0f) ? exp2f(__log2f(mean) / pe) : 0.0f;
        out[((size_t)b * O_DIM + o0 + g * 8 + o) * 4 + part] = gv;
    }
}

extern "C" void kernel_launch(void* const* d_in, const int* in_sizes, int n_in,
                              void* d_out, int out_size)
{
    const float* x    = (const float*)d_in[0];
    const int*   seqL = (const int*)d_in[1];
    const float* Wm   = (const float*)d_in[2];
    const float* p    = (const float*)d_in[3];
    float* out = (float*)d_out;

    seg_max_kernel<<<B_SEG * C_DIM, 352>>>(x, seqL);

    dim3 grid2(O_DIM / OW, B_SEG);
    conv_gem_kernel<<<grid2, 176>>>(Wm, p, out);
}